// round 1
// baseline (speedup 1.0000x reference)
#include <cuda_runtime.h>
#include <math.h>

#define Hh 2048
#define Bb 64
#define Ss 512
#define KC 128
#define NCTA 128   // column CTAs; each owns 16 columns
#define NT 16

// Static device scratch (no allocations allowed).
__device__ float g_W[Hh * Hh];      // 16 MB recurrent matrix
__device__ float g_n[Hh];
__device__ float g_m[Hh];
__device__ float g_r[2][Bb * Hh];   // double-buffered rates
__device__ float g_h[Bb * Hh];      // hidden state

// ---------------------------------------------------------------------------
// Kernel 1: compute n_rec, m_rec (single block)
// ---------------------------------------------------------------------------
__global__ void prep_nm_kernel(const float* __restrict__ wi,
                               const float* __restrict__ wo,
                               const float* __restrict__ A,
                               const float* __restrict__ owi,
                               const float* __restrict__ owo,
                               const float* __restrict__ omn) {
    __shared__ float reda[8], redb[8], s2[2];
    float a = 0.f, b = 0.f;
    for (int i = threadIdx.x; i < Hh; i += blockDim.x) {
        float u = wi[i]; a += u * u;
        float v = wo[i]; b += v * v;
    }
    for (int o = 16; o; o >>= 1) {
        a += __shfl_down_sync(0xffffffffu, a, o);
        b += __shfl_down_sync(0xffffffffu, b, o);
    }
    int w = threadIdx.x >> 5, l = threadIdx.x & 31;
    if (l == 0) { reda[w] = a; redb[w] = b; }
    __syncthreads();
    if (threadIdx.x == 0) {
        float sa = 0.f, sb = 0.f;
        int nw = blockDim.x >> 5;
        for (int i = 0; i < nw; i++) { sa += reda[i]; sb += redb[i]; }
        s2[0] = sa; s2[1] = sb;
    }
    __syncthreads();
    float hf  = (float)Hh;
    float cwi = owi[0] * hf / s2[0];
    float cwo = owo[0] * hf / s2[1];
    float cmn = sqrtf(omn[0] * hf);
    for (int i = threadIdx.x; i < Hh; i += blockDim.x) {
        g_n[i] = cwi * wi[i] + cmn * A[i];
        g_m[i] = cwo * wo[i] + cmn * A[i];
    }
}

// ---------------------------------------------------------------------------
// Kernel 2: W = n m^T / H + rec_noise
// ---------------------------------------------------------------------------
__global__ void build_w_kernel(const float* __restrict__ rec_noise) {
    int idx = blockIdx.x * blockDim.x + threadIdx.x;
    if (idx < Hh * Hh) {
        int k = idx >> 11;          // row
        int j = idx & (Hh - 1);     // col
        g_W[idx] = g_n[k] * g_m[j] * (1.0f / (float)Hh) + rec_noise[idx];
    }
}

// ---------------------------------------------------------------------------
// Kernel 3: init h, r
// ---------------------------------------------------------------------------
__global__ void init_kernel(const float* __restrict__ h0) {
    int idx = blockIdx.x * blockDim.x + threadIdx.x;
    if (idx < Bb * Hh) {
        int j = idx & (Hh - 1);
        float hv = h0[j];
        g_h[idx]    = hv;
        g_r[0][idx] = tanhf(hv);
    }
}

// ---------------------------------------------------------------------------
// Step kernel: h = 0.8h + 0.05 n_t + 0.2 (r@W + x_t wi^T); r = tanh(h)
// CTAs 0..127: 16 columns each. CTA 128: writes out[:, t-1] from r entering
// this step (deterministic, no atomics).
// ---------------------------------------------------------------------------
__global__ void __launch_bounds__(256) step_kernel(
    const float* __restrict__ x,      // [B,S,1]
    const float* __restrict__ noise,  // [B,S,H]
    const float* __restrict__ wi,     // [H]
    const float* __restrict__ wo,     // [H]
    float* __restrict__ out,          // [B,S,1]
    int t) {
    int cur = t & 1;
    const float* __restrict__ rin = g_r[cur];
    float* __restrict__ rout      = g_r[cur ^ 1];

    if (blockIdx.x == NCTA) {
        // out[:, t-1] = r_in @ wo / H   (r_in is r after step t-1)
        if (t == 0) return;
        int w = threadIdx.x >> 5, l = threadIdx.x & 31;
        for (int b = w; b < Bb; b += 8) {
            const float* rb = rin + b * Hh;
            float s = 0.f;
            for (int k = l; k < Hh; k += 32) s += rb[k] * wo[k];
            for (int o = 16; o; o >>= 1) s += __shfl_down_sync(0xffffffffu, s, o);
            if (l == 0) out[b * Ss + (t - 1)] = s * (1.0f / (float)Hh);
        }
        return;
    }

    __shared__ float rs[Bb][KC + 4];  // +4 pad: float4-aligned rows, no LDS conflicts

    const int col0 = blockIdx.x * NT;
    const int jt = threadIdx.x & 7;    // 8 groups x 2 cols
    const int bg = threadIdx.x >> 3;   // 32 groups x 2 rows
    const int j0 = col0 + jt * 2;
    const int b0 = bg * 2;

    float acc00 = 0.f, acc01 = 0.f, acc10 = 0.f, acc11 = 0.f;

    for (int k0 = 0; k0 < Hh; k0 += KC) {
        __syncthreads();
        // stage rin[0:64][k0:k0+KC] -> SMEM (8192 floats, float4 loads)
        {
            int tid = threadIdx.x;
#pragma unroll
            for (int it = 0; it < 8; it++) {
                int idx4 = it * 256 + tid;          // 0..2047
                int b  = idx4 >> 5;                 // 32 float4 per row
                int kk = (idx4 & 31) * 4;
                float4 v = *(const float4*)(rin + (size_t)b * Hh + k0 + kk);
                *(float4*)&rs[b][kk] = v;
            }
        }
        __syncthreads();

        const float* Wp = g_W + (size_t)k0 * Hh + j0;
#pragma unroll 8
        for (int k = 0; k < KC; k++) {
            float2 w2 = *(const float2*)Wp;
            Wp += Hh;
            float ra = rs[b0][k];
            float rb = rs[b0 + 1][k];
            acc00 = fmaf(ra, w2.x, acc00);
            acc01 = fmaf(ra, w2.y, acc01);
            acc10 = fmaf(rb, w2.x, acc10);
            acc11 = fmaf(rb, w2.y, acc11);
        }
    }

    // epilogue: h update, tanh, write next-r
    float xv0 = x[b0 * Ss + t];
    float xv1 = x[(b0 + 1) * Ss + t];
    float wj0 = wi[j0], wj1 = wi[j0 + 1];

    size_t i00 = (size_t)b0 * Hh + j0;
    size_t i10 = i00 + Hh;
    const float* np0 = noise + (size_t)b0 * ((size_t)Ss * Hh) + (size_t)t * Hh + j0;
    const float* np1 = np0 + (size_t)Ss * Hh;

    float h00 = 0.8f * g_h[i00]     + 0.05f * np0[0] + 0.2f * (acc00 + xv0 * wj0);
    float h01 = 0.8f * g_h[i00 + 1] + 0.05f * np0[1] + 0.2f * (acc01 + xv0 * wj1);
    float h10 = 0.8f * g_h[i10]     + 0.05f * np1[0] + 0.2f * (acc10 + xv1 * wj0);
    float h11 = 0.8f * g_h[i10 + 1] + 0.05f * np1[1] + 0.2f * (acc11 + xv1 * wj1);

    g_h[i00]     = h00;
    g_h[i00 + 1] = h01;
    g_h[i10]     = h10;
    g_h[i10 + 1] = h11;

    rout[i00]     = tanhf(h00);
    rout[i00 + 1] = tanhf(h01);
    rout[i10]     = tanhf(h10);
    rout[i10 + 1] = tanhf(h11);
}

// ---------------------------------------------------------------------------
// Final output for t = S-1 (r after the last step lives in g_r[0])
// ---------------------------------------------------------------------------
__global__ void final_out_kernel(const float* __restrict__ wo, float* __restrict__ out) {
    const float* rin = g_r[(Ss) & 1];  // Ss=512 even -> g_r[0]
    int w = threadIdx.x >> 5, l = threadIdx.x & 31;
    for (int b = w; b < Bb; b += 8) {
        const float* rb = rin + b * Hh;
        float s = 0.f;
        for (int k = l; k < Hh; k += 32) s += rb[k] * wo[k];
        for (int o = 16; o; o >>= 1) s += __shfl_down_sync(0xffffffffu, s, o);
        if (l == 0) out[b * Ss + (Ss - 1)] = s * (1.0f / (float)Hh);
    }
}

// ---------------------------------------------------------------------------
extern "C" void kernel_launch(void* const* d_in, const int* in_sizes, int n_in,
                              void* d_out, int out_size) {
    const float* x         = (const float*)d_in[0];
    const float* noise     = (const float*)d_in[1];
    const float* wi        = (const float*)d_in[2];
    const float* wo        = (const float*)d_in[3];
    const float* A         = (const float*)d_in[4];
    const float* rec_noise = (const float*)d_in[5];
    const float* owi       = (const float*)d_in[6];
    const float* owo       = (const float*)d_in[7];
    const float* omn       = (const float*)d_in[8];
    const float* h0        = (const float*)d_in[9];
    float* out = (float*)d_out;

    prep_nm_kernel<<<1, 256>>>(wi, wo, A, owi, owo, omn);
    build_w_kernel<<<(Hh * Hh) / 512, 512>>>(rec_noise);
    init_kernel<<<(Bb * Hh) / 512, 512>>>(h0);

    for (int t = 0; t < Ss; t++)
        step_kernel<<<NCTA + 1, 256>>>(x, noise, wi, wo, out, t);

    final_out_kernel<<<1, 256>>>(wo, out);
}

// round 2
// speedup vs baseline: 2.1145x; 2.1145x over previous
#include <cuda_runtime.h>
#include <math.h>

#define Hh 2048
#define Bb 64
#define Ss 512
#define NCTA 128          // column CTAs, each owns 16 cols; must be <= #SMs (148)
#define NT 16             // cols per CTA
#define KC 128            // k-chunk staged in SMEM
#define WPITCH 2052       // padded pitch for ws[j][k]
#define RPITCH 132        // padded pitch for rs[b][k]

// ---- static device scratch (no allocations allowed) ----
__device__ float g_r[2][Bb * Hh];            // double-buffered rates
__device__ float g_part[Ss][Bb][NCTA];       // per-CTA output partials (deterministic)
__device__ unsigned g_barcnt;                // grid barrier count
__device__ volatile unsigned g_bargen;       // grid barrier generation

// ---------------------------------------------------------------------------
// software grid barrier (all NCTA CTAs co-resident: grid <= #SMs)
// ---------------------------------------------------------------------------
__device__ __forceinline__ void grid_sync() {
    __threadfence();
    __syncthreads();
    if (threadIdx.x == 0) {
        unsigned gen = g_bargen;              // volatile read (my current gen)
        if (atomicAdd(&g_barcnt, 1u) == NCTA - 1) {
            g_barcnt = 0;
            __threadfence();
            g_bargen = gen + 1;               // release
        } else {
            while (g_bargen == gen) { }       // spin on L2 (volatile)
        }
    }
    __syncthreads();
}

// ---------------------------------------------------------------------------
// persistent RNN kernel: builds W slab in SMEM, runs all 512 steps with a
// device-wide barrier per step, then reduces output partials in the tail.
// ---------------------------------------------------------------------------
extern __shared__ float smem[];

__global__ void __launch_bounds__(256, 1) rnn_persist_kernel(
    const float* __restrict__ x,          // [B,S,1]
    const float* __restrict__ noise,      // [B,S,H]
    const float* __restrict__ wi,         // [H]
    const float* __restrict__ wo,         // [H]
    const float* __restrict__ Av,         // [H]
    const float* __restrict__ rec_noise,  // [H,H]
    const float* __restrict__ owi,
    const float* __restrict__ owo,
    const float* __restrict__ omn,
    const float* __restrict__ h0,         // [H]
    float* __restrict__ out)              // [B,S,1]
{
    float* ws  = smem;                    // [NT][WPITCH]   W slab, ws[j][k]
    float* rs  = ws + NT * WPITCH;        // [Bb][RPITCH]   r chunk
    float* red = rs + Bb * RPITCH;        // [64] scratch

    const int tid  = threadIdx.x;
    const int cta  = blockIdx.x;
    const int col0 = cta * NT;

    const int jg  = tid & 7;              // 8 j-groups of 2 cols
    const int bg  = tid >> 3;             // 32 b-groups of 2 rows
    const int j0l = jg * 2;               // local col
    const int j0g = col0 + j0l;           // global col
    const int b0  = bg * 2;

    // ---- prep: norms of wi, wo (redundant per CTA, cheap) ----
    {
        float sa = 0.f, sb = 0.f;
        for (int i = tid; i < Hh; i += 256) {
            float u = wi[i]; sa = fmaf(u, u, sa);
            float v = wo[i]; sb = fmaf(v, v, sb);
        }
        for (int o = 16; o; o >>= 1) {
            sa += __shfl_down_sync(0xffffffffu, sa, o);
            sb += __shfl_down_sync(0xffffffffu, sb, o);
        }
        if ((tid & 31) == 0) { red[tid >> 5] = sa; red[8 + (tid >> 5)] = sb; }
        __syncthreads();
        if (tid == 0) {
            float A2 = 0.f, B2 = 0.f;
            for (int i = 0; i < 8; i++) { A2 += red[i]; B2 += red[8 + i]; }
            red[16] = A2; red[17] = B2;
        }
        __syncthreads();
    }
    const float hf  = 2048.0f;
    const float cwi = owi[0] * hf / red[16];
    const float cwo = owo[0] * hf / red[17];
    const float cmn = sqrtf(omn[0] * hf);
    __syncthreads();

    // m values for this CTA's 16 columns
    if (tid < NT) red[32 + tid] = cwo * wo[col0 + tid] + cmn * Av[col0 + tid];
    __syncthreads();

    // ---- build W slab in SMEM: ws[j][k] = (n[k]/H)*m[j] + rec_noise[k][col0+j]
    {
        const float* ms = red + 32;
        const float invH = 1.0f / hf;
        float m0 = ms[0], m1 = ms[1], m2 = ms[2], m3 = ms[3];
        float m4 = ms[4], m5 = ms[5], m6 = ms[6], m7 = ms[7];
        float m8 = ms[8], m9 = ms[9], m10 = ms[10], m11 = ms[11];
        float m12 = ms[12], m13 = ms[13], m14 = ms[14], m15 = ms[15];
        for (int k = tid; k < Hh; k += 256) {
            float nk = (cwi * wi[k] + cmn * Av[k]) * invH;
            const float4* rn = (const float4*)(rec_noise + (size_t)k * Hh + col0);
            float4 q0 = rn[0], q1 = rn[1], q2 = rn[2], q3 = rn[3];
            float* wr = ws + k;
            wr[0  * WPITCH] = fmaf(nk, m0,  q0.x);
            wr[1  * WPITCH] = fmaf(nk, m1,  q0.y);
            wr[2  * WPITCH] = fmaf(nk, m2,  q0.z);
            wr[3  * WPITCH] = fmaf(nk, m3,  q0.w);
            wr[4  * WPITCH] = fmaf(nk, m4,  q1.x);
            wr[5  * WPITCH] = fmaf(nk, m5,  q1.y);
            wr[6  * WPITCH] = fmaf(nk, m6,  q1.z);
            wr[7  * WPITCH] = fmaf(nk, m7,  q1.w);
            wr[8  * WPITCH] = fmaf(nk, m8,  q2.x);
            wr[9  * WPITCH] = fmaf(nk, m9,  q2.y);
            wr[10 * WPITCH] = fmaf(nk, m10, q2.z);
            wr[11 * WPITCH] = fmaf(nk, m11, q2.w);
            wr[12 * WPITCH] = fmaf(nk, m12, q3.x);
            wr[13 * WPITCH] = fmaf(nk, m13, q3.y);
            wr[14 * WPITCH] = fmaf(nk, m14, q3.z);
            wr[15 * WPITCH] = fmaf(nk, m15, q3.w);
        }
        __syncthreads();
    }

    // ---- per-thread constants + register-resident h ----
    const float wj0  = wi[j0g], wj1  = wi[j0g + 1];
    const float woj0 = wo[j0g], woj1 = wo[j0g + 1];
    float h00 = h0[j0g], h01 = h0[j0g + 1];
    float h10 = h00,     h11 = h01;

    // ---- init r buffer 0 and sync the grid ----
    {
        float r0 = tanhf(h00), r1 = tanhf(h01);
        __stcg((float2*)&g_r[0][(size_t)b0 * Hh + j0g],       make_float2(r0, r1));
        __stcg((float2*)&g_r[0][(size_t)(b0 + 1) * Hh + j0g], make_float2(r0, r1));
    }
    grid_sync();

    // ---- main time loop ----
    const size_t nstride = (size_t)Ss * Hh;
    for (int t = 0; t < Ss; t++) {
        const float* __restrict__ rin = g_r[t & 1];
        float* __restrict__ rout      = g_r[(t & 1) ^ 1];

        float a00 = 0.f, a01 = 0.f, a10 = 0.f, a11 = 0.f;

        for (int kc = 0; kc < Hh / KC; kc++) {
            const int kb = kc * KC;
            __syncthreads();
            // stage rin[0:64][kb:kb+128] -> rs (L2-coherent loads)
            #pragma unroll
            for (int it = 0; it < 8; it++) {
                int idx4 = it * 256 + tid;       // 0..2047 float4s
                int b    = idx4 >> 5;
                int kk   = (idx4 & 31) * 4;
                float4 v = __ldcg((const float4*)(rin + (size_t)b * Hh + kb + kk));
                *(float4*)&rs[b * RPITCH + kk] = v;
            }
            __syncthreads();

            const float* wsp0 = ws + (size_t)j0l * WPITCH + kb;
            const float* wsp1 = wsp0 + WPITCH;
            const float* rp0  = rs + b0 * RPITCH;
            const float* rp1  = rp0 + RPITCH;
            #pragma unroll 8
            for (int k = 0; k < KC; k += 4) {
                float4 w0 = *(const float4*)(wsp0 + k);
                float4 w1 = *(const float4*)(wsp1 + k);
                float4 ra = *(const float4*)(rp0 + k);
                float4 rb = *(const float4*)(rp1 + k);
                a00 = fmaf(ra.x, w0.x, a00); a01 = fmaf(ra.x, w1.x, a01);
                a10 = fmaf(rb.x, w0.x, a10); a11 = fmaf(rb.x, w1.x, a11);
                a00 = fmaf(ra.y, w0.y, a00); a01 = fmaf(ra.y, w1.y, a01);
                a10 = fmaf(rb.y, w0.y, a10); a11 = fmaf(rb.y, w1.y, a11);
                a00 = fmaf(ra.z, w0.z, a00); a01 = fmaf(ra.z, w1.z, a01);
                a10 = fmaf(rb.z, w0.z, a10); a11 = fmaf(rb.z, w1.z, a11);
                a00 = fmaf(ra.w, w0.w, a00); a01 = fmaf(ra.w, w1.w, a01);
                a10 = fmaf(rb.w, w0.w, a10); a11 = fmaf(rb.w, w1.w, a11);
            }
        }

        // epilogue: h update, tanh, write next r, output partial
        const size_t nb0 = (size_t)b0 * nstride + (size_t)t * Hh + j0g;
        float2 n0 = *(const float2*)(noise + nb0);
        float2 n1 = *(const float2*)(noise + nb0 + nstride);
        float xv0 = x[b0 * Ss + t];
        float xv1 = x[(b0 + 1) * Ss + t];

        h00 = 0.8f * h00 + 0.05f * n0.x + 0.2f * (a00 + xv0 * wj0);
        h01 = 0.8f * h01 + 0.05f * n0.y + 0.2f * (a01 + xv0 * wj1);
        h10 = 0.8f * h10 + 0.05f * n1.x + 0.2f * (a10 + xv1 * wj0);
        h11 = 0.8f * h11 + 0.05f * n1.y + 0.2f * (a11 + xv1 * wj1);

        float r00 = tanhf(h00), r01 = tanhf(h01);
        float r10 = tanhf(h10), r11 = tanhf(h11);

        __stcg((float2*)&rout[(size_t)b0 * Hh + j0g],       make_float2(r00, r01));
        __stcg((float2*)&rout[(size_t)(b0 + 1) * Hh + j0g], make_float2(r10, r11));

        // output partials over this CTA's 16 cols: reduce across the 8 jg lanes
        float p0 = fmaf(r00, woj0, r01 * woj1);
        float p1 = fmaf(r10, woj0, r11 * woj1);
        #pragma unroll
        for (int o = 4; o; o >>= 1) {
            p0 += __shfl_down_sync(0xffffffffu, p0, o, 8);
            p1 += __shfl_down_sync(0xffffffffu, p1, o, 8);
        }
        if (jg == 0) {
            g_part[t][b0][cta]     = p0;
            g_part[t][b0 + 1][cta] = p1;
        }

        grid_sync();
    }

    // ---- tail: reduce partials -> out (deterministic; covers every element)
    {
        int pair = cta * 256 + tid;           // 0..32767 = Ss*Bb
        int tt = pair >> 6;
        int b  = pair & 63;
        const float* pp = &g_part[tt][b][0];
        float s = 0.f;
        #pragma unroll
        for (int c = 0; c < NCTA; c += 4) {
            float4 v = *(const float4*)(pp + c);
            s += (v.x + v.y) + (v.z + v.w);
        }
        out[b * Ss + tt] = s * (1.0f / 2048.0f);
    }
}

// ---------------------------------------------------------------------------
extern "C" void kernel_launch(void* const* d_in, const int* in_sizes, int n_in,
                              void* d_out, int out_size) {
    const float* x         = (const float*)d_in[0];
    const float* noise     = (const float*)d_in[1];
    const float* wi        = (const float*)d_in[2];
    const float* wo        = (const float*)d_in[3];
    const float* A         = (const float*)d_in[4];
    const float* rec_noise = (const float*)d_in[5];
    const float* owi       = (const float*)d_in[6];
    const float* owo       = (const float*)d_in[7];
    const float* omn       = (const float*)d_in[8];
    const float* h0        = (const float*)d_in[9];
    float* out = (float*)d_out;

    const int smem_bytes = (NT * WPITCH + Bb * RPITCH + 64) * sizeof(float);
    static int attr_done = 0;
    if (!attr_done) {
        cudaFuncSetAttribute(rnn_persist_kernel,
                             cudaFuncAttributeMaxDynamicSharedMemorySize, smem_bytes);
        attr_done = 1;
    }

    rnn_persist_kernel<<<NCTA, 256, smem_bytes>>>(
        x, noise, wi, wo, A, rec_noise, owi, owo, omn, h0, out);
}

// round 4
// speedup vs baseline: 5.7776x; 2.7324x over previous
#include <cuda_runtime.h>
#include <cuda_bf16.h>
#include <math.h>

#define Hh 2048
#define Bb 64
#define Ss 512
#define NCTA 128       // one CTA per 16 output columns
#define NT 16

// ---- static device scratch ----
__device__ unsigned int g_rb[2][Bb * Hh];     // packed r: lo16=bf16(hi part), hi16=bf16(residual)
__device__ float g_part[Ss][Bb][NCTA];        // per-CTA output partials
__device__ unsigned g_barcnt;
__device__ volatile unsigned g_bargen;

// ---------------------------------------------------------------------------
__device__ __forceinline__ void grid_sync() {
    __threadfence();
    __syncthreads();
    if (threadIdx.x == 0) {
        unsigned gen = g_bargen;
        if (atomicAdd(&g_barcnt, 1u) == NCTA - 1) {
            g_barcnt = 0;
            __threadfence();
            g_bargen = gen + 1;
        } else {
            while (g_bargen == gen) { }
        }
    }
    __syncthreads();
    __threadfence();
}

__device__ __forceinline__ unsigned pk2(__nv_bfloat16 a, __nv_bfloat16 b) {
    return (unsigned)__bfloat16_as_ushort(a) | ((unsigned)__bfloat16_as_ushort(b) << 16);
}

// pack value as (hi bf16 in low16, residual bf16 in high16)
__device__ __forceinline__ unsigned pack_split(float v) {
    __nv_bfloat16 h = __float2bfloat16(v);
    __nv_bfloat16 l = __float2bfloat16(v - __bfloat162float(h));
    return (unsigned)__bfloat16_as_ushort(h) | ((unsigned)__bfloat16_as_ushort(l) << 16);
}

__device__ __forceinline__ void mma16816(float& d0, float& d1, float& d2, float& d3,
                                         unsigned a0, unsigned a1, unsigned a2, unsigned a3,
                                         unsigned b0, unsigned b1) {
    asm volatile(
        "mma.sync.aligned.m16n8k16.row.col.f32.bf16.bf16.f32 "
        "{%0,%1,%2,%3},{%4,%5,%6,%7},{%8,%9},{%0,%1,%2,%3};\n"
        : "+f"(d0), "+f"(d1), "+f"(d2), "+f"(d3)
        : "r"(a0), "r"(a1), "r"(a2), "r"(a3), "r"(b0), "r"(b1));
}

// ---------------------------------------------------------------------------
extern __shared__ uint2 smem_u2[];

__global__ void __launch_bounds__(256, 1) rnn_mma_kernel(
    const float* __restrict__ x,          // [B,S,1]
    const float* __restrict__ noise,      // [B,S,H]
    const float* __restrict__ wi,         // [H]
    const float* __restrict__ wo,         // [H]
    const float* __restrict__ Av,         // [H]
    const float* __restrict__ rec_noise,  // [H,H]
    const float* __restrict__ owi,
    const float* __restrict__ owo,
    const float* __restrict__ omn,
    const float* __restrict__ h0,         // [H]
    float* __restrict__ out)              // [B,S,1]
{
    // SMEM: Wfrag[2 parts][128 kb][2 nb][32 lanes] uint2 = 131072 B; red 256 B; fred 4 KB
    uint2* Wfrag = smem_u2;                       // 16384 uint2
    float* red   = (float*)(smem_u2 + 16384);     // 64 floats
    float* fred  = red + 64;                      // 1024 floats

    const int tid  = threadIdx.x;
    const int cta  = blockIdx.x;
    const int col0 = cta * NT;
    const int wid  = tid >> 5;
    const int lane = tid & 31;
    const int g    = lane >> 2;
    const int tg   = lane & 3;
    const bool khigh = wid >= 4;
    const int m0   = (wid & 3) * 16;
    const int rowA = m0 + g;
    const int rowB = rowA + 8;
    const int kb0  = khigh ? 64 : 0;   // k16-block offset for this warp's k-half
    const int jA   = col0 + 2 * tg;         // nb0 cols jA, jA+1
    const int jB   = col0 + 8 + 2 * tg;     // nb1 cols jB, jB+1

    // ---- norms of wi, wo ----
    {
        float sa = 0.f, sb = 0.f;
        for (int i = tid; i < Hh; i += 256) {
            float u = wi[i]; sa = fmaf(u, u, sa);
            float v = wo[i]; sb = fmaf(v, v, sb);
        }
        for (int o = 16; o; o >>= 1) {
            sa += __shfl_down_sync(0xffffffffu, sa, o);
            sb += __shfl_down_sync(0xffffffffu, sb, o);
        }
        if (lane == 0) { red[wid] = sa; red[8 + wid] = sb; }
        __syncthreads();
        if (tid == 0) {
            float A2 = 0.f, B2 = 0.f;
            for (int i = 0; i < 8; i++) { A2 += red[i]; B2 += red[8 + i]; }
            red[16] = A2; red[17] = B2;
        }
        __syncthreads();
    }
    const float hf   = 2048.0f;
    const float invH = 1.0f / hf;
    const float cwi  = owi[0] * hf / red[16];
    const float cwo  = owo[0] * hf / red[17];
    const float cmn  = sqrtf(omn[0] * hf);
    __syncthreads();

    // ---- build W fragments (once): W[k][j] = n[k]*m[j]/H + rec_noise[k][j]
    // layout: slot s in [0,8192): kb=s>>6, nb=(s>>5)&1, ln=s&31 ; part1 at +8192
    for (int s = tid; s < 8192; s += 256) {
        int kb = s >> 6;
        int nb = (s >> 5) & 1;
        int ln = s & 31;
        int gg = ln >> 2, tt = ln & 3;
        int k0 = kb * 16 + 2 * tt;
        int j  = col0 + nb * 8 + gg;
        float mj = cwo * wo[j] + cmn * Av[j];
        float w0, w1, w2, w3;
        {
            int k = k0;
            float nk = (cwi * wi[k] + cmn * Av[k]) * invH;
            w0 = fmaf(nk, mj, rec_noise[(size_t)k * Hh + j]);
            k = k0 + 1;
            nk = (cwi * wi[k] + cmn * Av[k]) * invH;
            w1 = fmaf(nk, mj, rec_noise[(size_t)k * Hh + j]);
            k = k0 + 8;
            nk = (cwi * wi[k] + cmn * Av[k]) * invH;
            w2 = fmaf(nk, mj, rec_noise[(size_t)k * Hh + j]);
            k = k0 + 9;
            nk = (cwi * wi[k] + cmn * Av[k]) * invH;
            w3 = fmaf(nk, mj, rec_noise[(size_t)k * Hh + j]);
        }
        __nv_bfloat16 h0b = __float2bfloat16(w0), h1b = __float2bfloat16(w1);
        __nv_bfloat16 h2b = __float2bfloat16(w2), h3b = __float2bfloat16(w3);
        uint2 hi; hi.x = pk2(h0b, h1b); hi.y = pk2(h2b, h3b);
        __nv_bfloat16 l0 = __float2bfloat16(w0 - __bfloat162float(h0b));
        __nv_bfloat16 l1 = __float2bfloat16(w1 - __bfloat162float(h1b));
        __nv_bfloat16 l2 = __float2bfloat16(w2 - __bfloat162float(h2b));
        __nv_bfloat16 l3 = __float2bfloat16(w3 - __bfloat162float(h3b));
        uint2 lo; lo.x = pk2(l0, l1); lo.y = pk2(l2, l3);
        Wfrag[s]        = hi;
        Wfrag[8192 + s] = lo;
    }
    __syncthreads();

    // ---- per-thread constants + register h (owned by warps 0-3) ----
    const float wiA0 = wi[jA], wiA1 = wi[jA + 1];
    const float wiB0 = wi[jB], wiB1 = wi[jB + 1];
    const float woA0 = wo[jA], woA1 = wo[jA + 1];
    const float woB0 = wo[jB], woB1 = wo[jB + 1];

    float hA0 = h0[jA], hA1 = h0[jA + 1], hA2 = h0[jB], hA3 = h0[jB + 1];
    float hB0 = hA0,    hB1 = hA1,        hB2 = hA2,    hB3 = hA3;

    if (!khigh) {
        uint2 v;
        v.x = pack_split(tanhf(hA0)); v.y = pack_split(tanhf(hA1));
        *(uint2*)&g_rb[0][(size_t)rowA * Hh + jA] = v;
        v.x = pack_split(tanhf(hA2)); v.y = pack_split(tanhf(hA3));
        *(uint2*)&g_rb[0][(size_t)rowA * Hh + jB] = v;
        v.x = pack_split(tanhf(hB0)); v.y = pack_split(tanhf(hB1));
        *(uint2*)&g_rb[0][(size_t)rowB * Hh + jA] = v;
        v.x = pack_split(tanhf(hB2)); v.y = pack_split(tanhf(hB3));
        *(uint2*)&g_rb[0][(size_t)rowB * Hh + jB] = v;
    }
    grid_sync();

    const size_t nstride = (size_t)Ss * Hh;

    // ---- main time loop ----
    for (int t = 0; t < Ss; t++) {
        const unsigned* __restrict__ rin = g_rb[t & 1];
        unsigned* __restrict__ rout      = g_rb[(t & 1) ^ 1];

        // early loads (latency hidden under the MMA loop)
        float2 nA0, nA1, nB0, nB1;
        float xvA = 0.f, xvB = 0.f;
        if (!khigh) {
            const float* npA = noise + (size_t)rowA * nstride + (size_t)t * Hh;
            const float* npB = npA + 8 * nstride;
            nA0 = *(const float2*)(npA + jA);
            nA1 = *(const float2*)(npA + jB);
            nB0 = *(const float2*)(npB + jA);
            nB1 = *(const float2*)(npB + jB);
            xvA = x[rowA * Ss + t];
            xvB = x[rowB * Ss + t];
        }

        float d00 = 0.f, d01 = 0.f, d02 = 0.f, d03 = 0.f;   // nb0 tile
        float d10 = 0.f, d11 = 0.f, d12 = 0.f, d13 = 0.f;   // nb1 tile

        const uint2* pA = (const uint2*)(rin + (size_t)rowA * Hh) + kb0 * 8 + tg;
        const uint2* pB = (const uint2*)(rin + (size_t)rowB * Hh) + kb0 * 8 + tg;
        const uint2* wfh = Wfrag + (size_t)kb0 * 64 + lane;          // part hi
        const uint2* wfl = wfh + 8192;                               // part lo

        #pragma unroll 2
        for (int kb = 0; kb < 64; kb++) {
            uint2 uA0 = __ldcg(pA + kb * 8);
            uint2 uA1 = __ldcg(pA + kb * 8 + 4);
            uint2 uB0 = __ldcg(pB + kb * 8);
            uint2 uB1 = __ldcg(pB + kb * 8 + 4);
            uint2 wh0 = wfh[kb * 64];
            uint2 wh1 = wfh[kb * 64 + 32];
            uint2 wl0 = wfl[kb * 64];
            uint2 wl1 = wfl[kb * 64 + 32];

            unsigned ah0 = __byte_perm(uA0.x, uA0.y, 0x5410);
            unsigned ah1 = __byte_perm(uB0.x, uB0.y, 0x5410);
            unsigned ah2 = __byte_perm(uA1.x, uA1.y, 0x5410);
            unsigned ah3 = __byte_perm(uB1.x, uB1.y, 0x5410);
            unsigned al0 = __byte_perm(uA0.x, uA0.y, 0x7632);
            unsigned al1 = __byte_perm(uB0.x, uB0.y, 0x7632);
            unsigned al2 = __byte_perm(uA1.x, uA1.y, 0x7632);
            unsigned al3 = __byte_perm(uB1.x, uB1.y, 0x7632);

            mma16816(d00, d01, d02, d03, ah0, ah1, ah2, ah3, wh0.x, wh0.y);
            mma16816(d10, d11, d12, d13, ah0, ah1, ah2, ah3, wh1.x, wh1.y);
            mma16816(d00, d01, d02, d03, ah0, ah1, ah2, ah3, wl0.x, wl0.y);
            mma16816(d10, d11, d12, d13, ah0, ah1, ah2, ah3, wl1.x, wl1.y);
            mma16816(d00, d01, d02, d03, al0, al1, al2, al3, wh0.x, wh0.y);
            mma16816(d10, d11, d12, d13, al0, al1, al2, al3, wh1.x, wh1.y);
        }

        // k-half partial exchange
        if (khigh) {
            float* fp = fred + (wid - 4) * 256 + lane * 8;
            fp[0] = d00; fp[1] = d01; fp[2] = d02; fp[3] = d03;
            fp[4] = d10; fp[5] = d11; fp[6] = d12; fp[7] = d13;
        }
        __syncthreads();

        if (!khigh) {
            const float* fp = fred + wid * 256 + lane * 8;
            d00 += fp[0]; d01 += fp[1]; d02 += fp[2]; d03 += fp[3];
            d10 += fp[4]; d11 += fp[5]; d12 += fp[6]; d13 += fp[7];

            hA0 = 0.8f * hA0 + 0.05f * nA0.x + 0.2f * (d00 + xvA * wiA0);
            hA1 = 0.8f * hA1 + 0.05f * nA0.y + 0.2f * (d01 + xvA * wiA1);
            hB0 = 0.8f * hB0 + 0.05f * nB0.x + 0.2f * (d02 + xvB * wiA0);
            hB1 = 0.8f * hB1 + 0.05f * nB0.y + 0.2f * (d03 + xvB * wiA1);
            hA2 = 0.8f * hA2 + 0.05f * nA1.x + 0.2f * (d10 + xvA * wiB0);
            hA3 = 0.8f * hA3 + 0.05f * nA1.y + 0.2f * (d11 + xvA * wiB1);
            hB2 = 0.8f * hB2 + 0.05f * nB1.x + 0.2f * (d12 + xvB * wiB0);
            hB3 = 0.8f * hB3 + 0.05f * nB1.y + 0.2f * (d13 + xvB * wiB1);

            float rA0 = tanhf(hA0), rA1 = tanhf(hA1), rA2 = tanhf(hA2), rA3 = tanhf(hA3);
            float rB0 = tanhf(hB0), rB1 = tanhf(hB1), rB2 = tanhf(hB2), rB3 = tanhf(hB3);

            uint2 v;
            v.x = pack_split(rA0); v.y = pack_split(rA1);
            __stcg((uint2*)&rout[(size_t)rowA * Hh + jA], v);
            v.x = pack_split(rA2); v.y = pack_split(rA3);
            __stcg((uint2*)&rout[(size_t)rowA * Hh + jB], v);
            v.x = pack_split(rB0); v.y = pack_split(rB1);
            __stcg((uint2*)&rout[(size_t)rowB * Hh + jA], v);
            v.x = pack_split(rB2); v.y = pack_split(rB3);
            __stcg((uint2*)&rout[(size_t)rowB * Hh + jB], v);

            // out partial over this warp's 16 cols
            float pAo = fmaf(rA0, woA0, fmaf(rA1, woA1, fmaf(rA2, woB0, rA3 * woB1)));
            float pBo = fmaf(rB0, woA0, fmaf(rB1, woA1, fmaf(rB2, woB0, rB3 * woB1)));
            #pragma unroll
            for (int o = 2; o; o >>= 1) {
                pAo += __shfl_down_sync(0xffffffffu, pAo, o, 4);
                pBo += __shfl_down_sync(0xffffffffu, pBo, o, 4);
            }
            if (tg == 0) {
                g_part[t][rowA][cta] = pAo;
                g_part[t][rowB][cta] = pBo;
            }
        }
        grid_sync();
    }

    // ---- tail: reduce partials -> out ----
    {
        int pair = cta * 256 + tid;     // 0..32767 = Ss*Bb
        int tt = pair >> 6;
        int b  = pair & 63;
        const float* pp = &g_part[tt][b][0];
        float s = 0.f;
        #pragma unroll
        for (int c = 0; c < NCTA; c += 4) {
            float4 v = *(const float4*)(pp + c);
            s += (v.x + v.y) + (v.z + v.w);
        }
        out[b * Ss + tt] = s * (1.0f / 2048.0f);
    }
}

// ---------------------------------------------------------------------------
extern "C" void kernel_launch(void* const* d_in, const int* in_sizes, int n_in,
                              void* d_out, int out_size) {
    const float* x         = (const float*)d_in[0];
    const float* noise     = (const float*)d_in[1];
    const float* wi        = (const float*)d_in[2];
    const float* wo        = (const float*)d_in[3];
    const float* A         = (const float*)d_in[4];
    const float* rec_noise = (const float*)d_in[5];
    const float* owi       = (const float*)d_in[6];
    const float* owo       = (const float*)d_in[7];
    const float* omn       = (const float*)d_in[8];
    const float* h0        = (const float*)d_in[9];
    float* out = (float*)d_out;

    const int smem_bytes = 131072 + 64 * 4 + 1024 * 4;   // Wfrag + red + fred
    static int attr_done = 0;
    if (!attr_done) {
        cudaFuncSetAttribute(rnn_mma_kernel,
                             cudaFuncAttributeMaxDynamicSharedMemorySize, smem_bytes);
        attr_done = 1;
    }

    rnn_mma_kernel<<<NCTA, 256, smem_bytes>>>(
        x, noise, wi, wo, A, rec_noise, owi, owo, omn, h0, out);
}

// round 5
// speedup vs baseline: 9.4817x; 1.6411x over previous
#include <cuda_runtime.h>
#include <cuda_bf16.h>
#include <math.h>

#define Hh 2048
#define Bb 64
#define Ss 512
#define NCTA 128       // one CTA per 16 output columns
#define NT 16

// ---- static device scratch ----
// packed r, PERMUTED layout: per row (1024 uint2), uint2 slot kb*8 + tg*2 + s
// holds element pair k = 16*kb + 8*s + 2*tg (each elem: lo16=bf16 hi, hi16=bf16 residual)
__device__ unsigned int g_rb[2][Bb * Hh];
__device__ float g_part[Ss][Bb][NCTA];        // per-CTA output partials
__device__ unsigned g_barcnt;
__device__ volatile unsigned g_bargen;

// ---------------------------------------------------------------------------
__device__ __forceinline__ void grid_sync() {
    __threadfence();
    __syncthreads();
    if (threadIdx.x == 0) {
        unsigned gen = g_bargen;
        if (atomicAdd(&g_barcnt, 1u) == NCTA - 1) {
            g_barcnt = 0;
            __threadfence();
            g_bargen = gen + 1;
        } else {
            while (g_bargen == gen) { }
        }
    }
    __syncthreads();
    __threadfence();
}

__device__ __forceinline__ unsigned pk2(__nv_bfloat16 a, __nv_bfloat16 b) {
    return (unsigned)__bfloat16_as_ushort(a) | ((unsigned)__bfloat16_as_ushort(b) << 16);
}

__device__ __forceinline__ unsigned pack_split(float v) {
    __nv_bfloat16 h = __float2bfloat16(v);
    __nv_bfloat16 l = __float2bfloat16(v - __bfloat162float(h));
    return (unsigned)__bfloat16_as_ushort(h) | ((unsigned)__bfloat16_as_ushort(l) << 16);
}

__device__ __forceinline__ void mma16816(float& d0, float& d1, float& d2, float& d3,
                                         unsigned a0, unsigned a1, unsigned a2, unsigned a3,
                                         unsigned b0, unsigned b1) {
    asm volatile(
        "mma.sync.aligned.m16n8k16.row.col.f32.bf16.bf16.f32 "
        "{%0,%1,%2,%3},{%4,%5,%6,%7},{%8,%9},{%0,%1,%2,%3};\n"
        : "+f"(d0), "+f"(d1), "+f"(d2), "+f"(d3)
        : "r"(a0), "r"(a1), "r"(a2), "r"(a3), "r"(b0), "r"(b1));
}

// ---------------------------------------------------------------------------
extern __shared__ uint4 smem_u4[];

__global__ void __launch_bounds__(256, 1) rnn_mma_kernel(
    const float* __restrict__ x,          // [B,S,1]
    const float* __restrict__ noise,      // [B,S,H]
    const float* __restrict__ wi,         // [H]
    const float* __restrict__ wo,         // [H]
    const float* __restrict__ Av,         // [H]
    const float* __restrict__ rec_noise,  // [H,H]
    const float* __restrict__ owi,
    const float* __restrict__ owo,
    const float* __restrict__ omn,
    const float* __restrict__ h0,         // [H]
    float* __restrict__ out)              // [B,S,1]
{
    // SMEM: WfragH[128 kb][32 lanes] uint4 = {b0,b1 tile0 | b0,b1 tile1} (hi part)
    //       WfragL same (lo part); red 256B; fred 4KB
    uint4* WfragH = smem_u4;                 // 4096 uint4 (64 KB)
    uint4* WfragL = WfragH + 4096;           // 4096 uint4 (64 KB)
    float* red    = (float*)(WfragL + 4096); // 64 floats
    float* fred   = red + 64;                // 1024 floats

    const int tid  = threadIdx.x;
    const int cta  = blockIdx.x;
    const int col0 = cta * NT;
    const int wid  = tid >> 5;
    const int lane = tid & 31;
    const int g    = lane >> 2;
    const int tg   = lane & 3;
    const bool khigh = wid >= 4;
    const int m0   = (wid & 3) * 16;
    const int rowA = m0 + g;
    const int rowB = rowA + 8;
    const int kb0  = khigh ? 64 : 0;        // k16-block offset for this warp's k-half
    const int jA   = col0 + 2 * tg;         // tile0 cols jA, jA+1
    const int jB   = col0 + 8 + 2 * tg;     // tile1 cols jB, jB+1

    // ---- norms of wi, wo ----
    {
        float sa = 0.f, sb = 0.f;
        for (int i = tid; i < Hh; i += 256) {
            float u = wi[i]; sa = fmaf(u, u, sa);
            float v = wo[i]; sb = fmaf(v, v, sb);
        }
        for (int o = 16; o; o >>= 1) {
            sa += __shfl_down_sync(0xffffffffu, sa, o);
            sb += __shfl_down_sync(0xffffffffu, sb, o);
        }
        if (lane == 0) { red[wid] = sa; red[8 + wid] = sb; }
        __syncthreads();
        if (tid == 0) {
            float A2 = 0.f, B2 = 0.f;
            for (int i = 0; i < 8; i++) { A2 += red[i]; B2 += red[8 + i]; }
            red[16] = A2; red[17] = B2;
        }
        __syncthreads();
    }
    const float hf   = 2048.0f;
    const float invH = 1.0f / hf;
    const float cwi  = owi[0] * hf / red[16];
    const float cwo  = owo[0] * hf / red[17];
    const float cmn  = sqrtf(omn[0] * hf);
    __syncthreads();

    // ---- build W fragments (once): W[k][j] = n[k]*m[j]/H + rec_noise[k][j]
    // slot s: kb=s>>6, nb=(s>>5)&1, ln=s&31 ; uint2 written at kb*64 + ln*2 + nb
    {
        uint2* WH2 = (uint2*)WfragH;
        uint2* WL2 = (uint2*)WfragL;
        for (int s = tid; s < 8192; s += 256) {
            int kb = s >> 6;
            int nb = (s >> 5) & 1;
            int ln = s & 31;
            int gg = ln >> 2, tt = ln & 3;
            int k0 = kb * 16 + 2 * tt;
            int j  = col0 + nb * 8 + gg;
            float mj = cwo * wo[j] + cmn * Av[j];
            float w0, w1, w2, w3;
            {
                int k = k0;
                float nk = (cwi * wi[k] + cmn * Av[k]) * invH;
                w0 = fmaf(nk, mj, rec_noise[(size_t)k * Hh + j]);
                k = k0 + 1;
                nk = (cwi * wi[k] + cmn * Av[k]) * invH;
                w1 = fmaf(nk, mj, rec_noise[(size_t)k * Hh + j]);
                k = k0 + 8;
                nk = (cwi * wi[k] + cmn * Av[k]) * invH;
                w2 = fmaf(nk, mj, rec_noise[(size_t)k * Hh + j]);
                k = k0 + 9;
                nk = (cwi * wi[k] + cmn * Av[k]) * invH;
                w3 = fmaf(nk, mj, rec_noise[(size_t)k * Hh + j]);
            }
            __nv_bfloat16 h0b = __float2bfloat16(w0), h1b = __float2bfloat16(w1);
            __nv_bfloat16 h2b = __float2bfloat16(w2), h3b = __float2bfloat16(w3);
            uint2 hi; hi.x = pk2(h0b, h1b); hi.y = pk2(h2b, h3b);
            __nv_bfloat16 l0 = __float2bfloat16(w0 - __bfloat162float(h0b));
            __nv_bfloat16 l1 = __float2bfloat16(w1 - __bfloat162float(h1b));
            __nv_bfloat16 l2 = __float2bfloat16(w2 - __bfloat162float(h2b));
            __nv_bfloat16 l3 = __float2bfloat16(w3 - __bfloat162float(h3b));
            uint2 lo; lo.x = pk2(l0, l1); lo.y = pk2(l2, l3);
            int slot = kb * 64 + ln * 2 + nb;
            WH2[slot] = hi;
            WL2[slot] = lo;
        }
        __syncthreads();
    }

    // ---- per-thread constants + register h (owned by warps 0-3) ----
    const float wiA0 = wi[jA], wiA1 = wi[jA + 1];
    const float wiB0 = wi[jB], wiB1 = wi[jB + 1];
    const float woA0 = wo[jA], woA1 = wo[jA + 1];
    const float woB0 = wo[jB], woB1 = wo[jB + 1];

    float hA0 = h0[jA], hA1 = h0[jA + 1], hA2 = h0[jB], hA3 = h0[jB + 1];
    float hB0 = hA0,    hB1 = hA1,        hB2 = hA2,    hB3 = hA3;

    if (!khigh) {
        // permuted uint4 write: uint4 index row*512 + cta*4 + tg holds
        // elements {jA, jA+1, jB, jB+1}
        uint4 v;
        v.x = pack_split(tanhf(hA0)); v.y = pack_split(tanhf(hA1));
        v.z = pack_split(tanhf(hA2)); v.w = pack_split(tanhf(hA3));
        *((uint4*)&g_rb[0][0] + (size_t)rowA * 512 + cta * 4 + tg) = v;
        v.x = pack_split(tanhf(hB0)); v.y = pack_split(tanhf(hB1));
        v.z = pack_split(tanhf(hB2)); v.w = pack_split(tanhf(hB3));
        *((uint4*)&g_rb[0][0] + (size_t)rowB * 512 + cta * 4 + tg) = v;
    }
    grid_sync();

    const size_t nstride = (size_t)Ss * Hh;

    // ---- main time loop ----
    for (int t = 0; t < Ss; t++) {
        const uint4* __restrict__ rin = (const uint4*)&g_rb[t & 1][0];
        uint4* __restrict__ routq     = (uint4*)&g_rb[(t & 1) ^ 1][0];

        // early loads (latency hidden under the MMA loop)
        float2 nA0, nA1, nB0, nB1;
        float xvA = 0.f, xvB = 0.f;
        if (!khigh) {
            const float* npA = noise + (size_t)rowA * nstride + (size_t)t * Hh;
            const float* npB = npA + 8 * nstride;
            nA0 = *(const float2*)(npA + jA);
            nA1 = *(const float2*)(npA + jB);
            nB0 = *(const float2*)(npB + jA);
            nB1 = *(const float2*)(npB + jB);
            xvA = x[rowA * Ss + t];
            xvB = x[rowB * Ss + t];
        }

        float d00 = 0.f, d01 = 0.f, d02 = 0.f, d03 = 0.f;   // tile0 (cols jA)
        float d10 = 0.f, d11 = 0.f, d12 = 0.f, d13 = 0.f;   // tile1 (cols jB)

        const uint4* pA = rin + (size_t)rowA * 512 + kb0 * 4 + tg;
        const uint4* pB = rin + (size_t)rowB * 512 + kb0 * 4 + tg;
        const uint4* wfh = WfragH + (size_t)kb0 * 32 + lane;
        const uint4* wfl = WfragL + (size_t)kb0 * 32 + lane;

        // depth-2 software prefetch of A fragments
        uint4 pfA[2], pfB[2];
        pfA[0] = __ldcg(pA);     pfB[0] = __ldcg(pB);
        pfA[1] = __ldcg(pA + 4); pfB[1] = __ldcg(pB + 4);

        #pragma unroll 4
        for (int kb = 0; kb < 64; kb++) {
            uint4 aA = pfA[kb & 1];
            uint4 aB = pfB[kb & 1];
            if (kb < 62) {
                pfA[kb & 1] = __ldcg(pA + (kb + 2) * 4);
                pfB[kb & 1] = __ldcg(pB + (kb + 2) * 4);
            }
            uint4 wh = wfh[kb * 32];
            uint4 wl = wfl[kb * 32];

            // aA = {klow pair, khigh pair} for rowA; each elem packed (hi|lo)
            unsigned ah0 = __byte_perm(aA.x, aA.y, 0x5410);
            unsigned ah1 = __byte_perm(aB.x, aB.y, 0x5410);
            unsigned ah2 = __byte_perm(aA.z, aA.w, 0x5410);
            unsigned ah3 = __byte_perm(aB.z, aB.w, 0x5410);
            unsigned al0 = __byte_perm(aA.x, aA.y, 0x7632);
            unsigned al1 = __byte_perm(aB.x, aB.y, 0x7632);
            unsigned al2 = __byte_perm(aA.z, aA.w, 0x7632);
            unsigned al3 = __byte_perm(aB.z, aB.w, 0x7632);

            mma16816(d00, d01, d02, d03, ah0, ah1, ah2, ah3, wh.x, wh.y);
            mma16816(d10, d11, d12, d13, ah0, ah1, ah2, ah3, wh.z, wh.w);
            mma16816(d00, d01, d02, d03, ah0, ah1, ah2, ah3, wl.x, wl.y);
            mma16816(d10, d11, d12, d13, ah0, ah1, ah2, ah3, wl.z, wl.w);
            mma16816(d00, d01, d02, d03, al0, al1, al2, al3, wh.x, wh.y);
            mma16816(d10, d11, d12, d13, al0, al1, al2, al3, wh.z, wh.w);
        }

        // k-half partial exchange
        if (khigh) {
            float* fp = fred + (wid - 4) * 256 + lane * 8;
            fp[0] = d00; fp[1] = d01; fp[2] = d02; fp[3] = d03;
            fp[4] = d10; fp[5] = d11; fp[6] = d12; fp[7] = d13;
        }
        __syncthreads();

        if (!khigh) {
            const float* fp = fred + wid * 256 + lane * 8;
            d00 += fp[0]; d01 += fp[1]; d02 += fp[2]; d03 += fp[3];
            d10 += fp[4]; d11 += fp[5]; d12 += fp[6]; d13 += fp[7];

            hA0 = 0.8f * hA0 + 0.05f * nA0.x + 0.2f * (d00 + xvA * wiA0);
            hA1 = 0.8f * hA1 + 0.05f * nA0.y + 0.2f * (d01 + xvA * wiA1);
            hB0 = 0.8f * hB0 + 0.05f * nB0.x + 0.2f * (d02 + xvB * wiA0);
            hB1 = 0.8f * hB1 + 0.05f * nB0.y + 0.2f * (d03 + xvB * wiA1);
            hA2 = 0.8f * hA2 + 0.05f * nA1.x + 0.2f * (d10 + xvA * wiB0);
            hA3 = 0.8f * hA3 + 0.05f * nA1.y + 0.2f * (d11 + xvA * wiB1);
            hB2 = 0.8f * hB2 + 0.05f * nB1.x + 0.2f * (d12 + xvB * wiB0);
            hB3 = 0.8f * hB3 + 0.05f * nB1.y + 0.2f * (d13 + xvB * wiB1);

            float rA0 = tanhf(hA0), rA1 = tanhf(hA1), rA2 = tanhf(hA2), rA3 = tanhf(hA3);
            float rB0 = tanhf(hB0), rB1 = tanhf(hB1), rB2 = tanhf(hB2), rB3 = tanhf(hB3);

            uint4 v;
            v.x = pack_split(rA0); v.y = pack_split(rA1);
            v.z = pack_split(rA2); v.w = pack_split(rA3);
            __stcg(routq + (size_t)rowA * 512 + cta * 4 + tg, v);
            v.x = pack_split(rB0); v.y = pack_split(rB1);
            v.z = pack_split(rB2); v.w = pack_split(rB3);
            __stcg(routq + (size_t)rowB * 512 + cta * 4 + tg, v);

            // out partial over this warp's 16 cols
            float pAo = fmaf(rA0, woA0, fmaf(rA1, woA1, fmaf(rA2, woB0, rA3 * woB1)));
            float pBo = fmaf(rB0, woA0, fmaf(rB1, woA1, fmaf(rB2, woB0, rB3 * woB1)));
            #pragma unroll
            for (int o = 2; o; o >>= 1) {
                pAo += __shfl_down_sync(0xffffffffu, pAo, o, 4);
                pBo += __shfl_down_sync(0xffffffffu, pBo, o, 4);
            }
            if (tg == 0) {
                g_part[t][rowA][cta] = pAo;
                g_part[t][rowB][cta] = pBo;
            }
        }
        grid_sync();
    }

    // ---- tail: reduce partials -> out ----
    {
        int pair = cta * 256 + tid;     // 0..32767 = Ss*Bb
        int tt = pair >> 6;
        int b  = pair & 63;
        const float* pp = &g_part[tt][b][0];
        float s = 0.f;
        #pragma unroll
        for (int c = 0; c < NCTA; c += 4) {
            float4 v = *(const float4*)(pp + c);
            s += (v.x + v.y) + (v.z + v.w);
        }
        out[b * Ss + tt] = s * (1.0f / 2048.0f);
    }
}

// ---------------------------------------------------------------------------
extern "C" void kernel_launch(void* const* d_in, const int* in_sizes, int n_in,
                              void* d_out, int out_size) {
    const float* x         = (const float*)d_in[0];
    const float* noise     = (const float*)d_in[1];
    const float* wi        = (const float*)d_in[2];
    const float* wo        = (const float*)d_in[3];
    const float* A         = (const float*)d_in[4];
    const float* rec_noise = (const float*)d_in[5];
    const float* owi       = (const float*)d_in[6];
    const float* owo       = (const float*)d_in[7];
    const float* omn       = (const float*)d_in[8];
    const float* h0        = (const float*)d_in[9];
    float* out = (float*)d_out;

    const int smem_bytes = 131072 + 64 * 4 + 1024 * 4;   // WfragH/L + red + fred
    static int attr_done = 0;
    if (!attr_done) {
        cudaFuncSetAttribute(rnn_mma_kernel,
                             cudaFuncAttributeMaxDynamicSharedMemorySize, smem_bytes);
        attr_done = 1;
    }

    rnn_mma_kernel<<<NCTA, 256, smem_bytes>>>(
        x, noise, wi, wo, A, rec_noise, owi, owo, omn, h0, out);
}